// round 1
// baseline (speedup 1.0000x reference)
#include <cuda_runtime.h>
#include <math.h>
#include <stdint.h>

#define BM 128
#define BN 128
#define BK 16
#define SA_ST 20    // smem A row stride (floats): conflict-free for frag loads
#define SB_ST 136   // smem B row stride (floats): conflict-free for frag loads

#define B_DIM 8192
#define H_DIM 2048
#define K_DIM 2048

// Scratch (device globals: allocation-free per harness rules)
__device__ float g_S1[(size_t)B_DIM * 8192];  // [z | r | u | cand_x]
__device__ float g_S2[(size_t)B_DIM * 6144];  // [z2 | r2 | cand2]
__device__ float g_hd[(size_t)B_DIM * H_DIM]; // h_new - h

struct GemmArgs {
    const float* A[3];
    const float* W[3];
    const float* b[3];
    int ldw[3];
    int ahd[3];   // A[i] is the g_hd scratch buffer
    int nA;
    int cbuf;     // 0 -> g_S1, 1 -> g_S2
    int coff;
    int ldc;
};

__device__ __forceinline__ uint32_t f2tf(float f) {
    uint32_t u;
    asm("cvt.rna.tf32.f32 %0, %1;" : "=r"(u) : "f"(f));
    return u;
}

__device__ __forceinline__ void mma8(float c[4], const uint32_t a[4], const uint32_t b[2]) {
    asm volatile(
        "mma.sync.aligned.m16n8k8.row.col.f32.tf32.tf32.f32 "
        "{%0,%1,%2,%3}, {%4,%5,%6,%7}, {%8,%9}, {%0,%1,%2,%3};\n"
        : "+f"(c[0]), "+f"(c[1]), "+f"(c[2]), "+f"(c[3])
        : "r"(a[0]), "r"(a[1]), "r"(a[2]), "r"(a[3]), "r"(b[0]), "r"(b[1]));
}

// C[M,N] = sum_i A_i[M,2048] @ W_i[2048,N] + sum_i b_i   (M=8192, N=2048 per launch)
__global__ __launch_bounds__(256, 1)
void gemm_tf32_kernel(GemmArgs args) {
    __shared__ uint32_t sA[2][BM * SA_ST];
    __shared__ uint32_t sB[2][BK * SB_ST];

    const int tid  = threadIdx.x;
    const int lane = tid & 31;
    const int warp = tid >> 5;
    const int wm = warp & 1;   // 2 warps along M
    const int wn = warp >> 1;  // 4 warps along N
    const int m0 = blockIdx.y * BM;
    const int n0 = blockIdx.x * BN;

    float* Cbase = (args.cbuf ? g_S2 : g_S1) + args.coff;

    float acc[4][4][4];
#pragma unroll
    for (int i = 0; i < 4; i++)
#pragma unroll
        for (int j = 0; j < 4; j++)
#pragma unroll
            for (int k = 0; k < 4; k++) acc[i][j][k] = 0.f;

    // global-load staging
    float4 aR[2], bR[2];
    const int aRow0 = tid >> 2;          // rows 0..63 / 64..127
    const int aCol  = (tid & 3) << 2;    // float col 0/4/8/12
    const int bRow0 = tid >> 5;          // rows 0..7 / 8..15
    const int bCol  = (tid & 31) << 2;   // float col 0..124

    const int iters = args.nA << 7;      // nA * (2048/16)

    auto gload = [&](int it) {
        int a  = it >> 7;
        int k0 = (it & 127) * BK;
        const float* A = args.ahd[a] ? g_hd : args.A[a];
        const float* W = args.W[a];
        int ldw = args.ldw[a];
#pragma unroll
        for (int i = 0; i < 2; i++)
            aR[i] = *(const float4*)(A + (size_t)(m0 + aRow0 + i * 64) * K_DIM + k0 + aCol);
#pragma unroll
        for (int i = 0; i < 2; i++)
            bR[i] = *(const float4*)(W + (size_t)(k0 + bRow0 + i * 8) * ldw + n0 + bCol);
    };

    auto sstore = [&](int buf) {
#pragma unroll
        for (int i = 0; i < 2; i++) {
            uint4 v = make_uint4(f2tf(aR[i].x), f2tf(aR[i].y), f2tf(aR[i].z), f2tf(aR[i].w));
            *(uint4*)&sA[buf][(aRow0 + i * 64) * SA_ST + aCol] = v;
        }
#pragma unroll
        for (int i = 0; i < 2; i++) {
            uint4 v = make_uint4(f2tf(bR[i].x), f2tf(bR[i].y), f2tf(bR[i].z), f2tf(bR[i].w));
            *(uint4*)&sB[buf][(bRow0 + i * 8) * SB_ST + bCol] = v;
        }
    };

    auto compute = [&](int buf) {
#pragma unroll
        for (int ks = 0; ks < 2; ks++) {
            uint32_t af[4][4], bf[4][2];
            const int kc = ks * 8 + (lane & 3);
#pragma unroll
            for (int mt = 0; mt < 4; mt++) {
                int r = wm * 64 + mt * 16 + (lane >> 2);
                af[mt][0] = sA[buf][r * SA_ST + kc];
                af[mt][1] = sA[buf][(r + 8) * SA_ST + kc];
                af[mt][2] = sA[buf][r * SA_ST + kc + 4];
                af[mt][3] = sA[buf][(r + 8) * SA_ST + kc + 4];
            }
#pragma unroll
            for (int nt = 0; nt < 4; nt++) {
                int c = wn * 32 + nt * 8 + (lane >> 2);
                bf[nt][0] = sB[buf][kc * SB_ST + c];
                bf[nt][1] = sB[buf][(kc + 4) * SB_ST + c];
            }
#pragma unroll
            for (int mt = 0; mt < 4; mt++)
#pragma unroll
                for (int nt = 0; nt < 4; nt++)
                    mma8(acc[mt][nt], af[mt], bf[nt]);
        }
    };

    // pipeline: prologue
    gload(0);
    sstore(0);
    __syncthreads();

    int buf = 0;
    for (int it = 0; it < iters; it++) {
        bool has = (it + 1) < iters;
        if (has) gload(it + 1);
        compute(buf);
        if (has) {
            sstore(buf ^ 1);
            __syncthreads();
            buf ^= 1;
        }
    }

    // epilogue: add summed biases, write fp32
#pragma unroll
    for (int nt = 0; nt < 4; nt++) {
        int colL = n0 + wn * 32 + nt * 8 + 2 * (lane & 3);
        float bs0 = 0.f, bs1 = 0.f;
        for (int a = 0; a < args.nA; a++) {
            bs0 += args.b[a][colL];
            bs1 += args.b[a][colL + 1];
        }
#pragma unroll
        for (int mt = 0; mt < 4; mt++) {
            int r = m0 + wm * 64 + mt * 16 + (lane >> 2);
            float2 v0 = make_float2(acc[mt][nt][0] + bs0, acc[mt][nt][1] + bs1);
            float2 v1 = make_float2(acc[mt][nt][2] + bs0, acc[mt][nt][3] + bs1);
            *(float2*)(Cbase + (size_t)r * args.ldc + colL) = v0;
            *(float2*)(Cbase + (size_t)(r + 8) * args.ldc + colL) = v1;
        }
    }
}

__device__ __forceinline__ float sigm(float x) { return 1.f / (1.f + expf(-x)); }

__global__ void epi1_kernel(const float* __restrict__ h, const float* __restrict__ g,
                            float* __restrict__ hnew) {
    size_t e0 = ((size_t)blockIdx.x * blockDim.x + threadIdx.x) * 4;
    if (e0 >= (size_t)B_DIM * H_DIM) return;
    size_t b = e0 >> 11, j = e0 & 2047;
    const float* row = g_S1 + b * 8192 + j;
    float4 zp = *(const float4*)(row);
    float4 rp = *(const float4*)(row + 2048);
    float4 up = *(const float4*)(row + 4096);
    float4 cp = *(const float4*)(row + 6144);
    float4 hv = *(const float4*)(h + e0);
    float4 gv = *(const float4*)(g + e0);
    float4 hn, hd;
#define DO1(f)                                                         \
    {                                                                  \
        float z = sigm(zp.f), r = sigm(rp.f), u = sigm(up.f);          \
        float cand = tanhf(cp.f + r * hv.f + u * gv.f);                \
        hn.f = (1.f - z) * hv.f + z * cand;                            \
        hd.f = hn.f - hv.f;                                            \
    }
    DO1(x) DO1(y) DO1(z) DO1(w)
#undef DO1
    *(float4*)(hnew + e0) = hn;
    *(float4*)(g_hd + e0) = hd;
}

__global__ void epi2_kernel(const float* __restrict__ g, float* __restrict__ gnew) {
    size_t e0 = ((size_t)blockIdx.x * blockDim.x + threadIdx.x) * 4;
    if (e0 >= (size_t)B_DIM * H_DIM) return;
    size_t b = e0 >> 11, j = e0 & 2047;
    const float* row = g_S2 + b * 6144 + j;
    float4 zp = *(const float4*)(row);
    float4 rp = *(const float4*)(row + 2048);
    float4 cp = *(const float4*)(row + 4096);
    float4 gv = *(const float4*)(g + e0);
    float4 gn;
#define DO2(f)                                              \
    {                                                       \
        float z = sigm(zp.f), r = sigm(rp.f);               \
        float cand = tanhf(cp.f + r * gv.f);                \
        gn.f = (1.f - z) * gv.f + z * cand;                 \
    }
    DO2(x) DO2(y) DO2(z) DO2(w)
#undef DO2
    *(float4*)(gnew + e0) = gn;
}

static void launch_gemm(int nA,
                        const float* A0, int ahd0, const float* W0, const float* b0, int l0,
                        const float* A1, int ahd1, const float* W1, const float* b1, int l1,
                        const float* A2, int ahd2, const float* W2, const float* b2, int l2,
                        int cbuf, int coff, int ldc) {
    GemmArgs ga;
    ga.A[0] = A0; ga.A[1] = A1; ga.A[2] = A2;
    ga.W[0] = W0; ga.W[1] = W1; ga.W[2] = W2;
    ga.b[0] = b0; ga.b[1] = b1; ga.b[2] = b2;
    ga.ldw[0] = l0; ga.ldw[1] = l1; ga.ldw[2] = l2;
    ga.ahd[0] = ahd0; ga.ahd[1] = ahd1; ga.ahd[2] = ahd2;
    ga.nA = nA; ga.cbuf = cbuf; ga.coff = coff; ga.ldc = ldc;
    dim3 grid(H_DIM / BN, B_DIM / BM), blk(256);
    gemm_tf32_kernel<<<grid, blk>>>(ga);
}

extern "C" void kernel_launch(void* const* d_in, const int* in_sizes, int n_in,
                              void* d_out, int out_size) {
    (void)in_sizes; (void)n_in; (void)out_size;
    const float* x   = (const float*)d_in[0];
    const float* h   = (const float*)d_in[1];
    const float* g   = (const float*)d_in[2];
    const float* Wx  = (const float*)d_in[3];
    const float* bx  = (const float*)d_in[4];
    const float* Wh  = (const float*)d_in[5];
    const float* bh  = (const float*)d_in[6];
    const float* Wgh = (const float*)d_in[7];
    const float* bgh = (const float*)d_in[8];
    const float* Whd = (const float*)d_in[9];
    const float* bhd = (const float*)d_in[10];
    const float* Wg  = (const float*)d_in[11];
    const float* bg  = (const float*)d_in[12];

    float* out  = (float*)d_out;
    float* hnew = out;
    float* gnew = out + (size_t)B_DIM * H_DIM;

    const int H = H_DIM;

    // Stage 1: S1 = [z | r | u | cand_x], each 2048 wide (ldc 8192)
    // z: x@Wx[:,0:H] + h@Wh[:,0:H] + g@Wgh[:,0:H]
    launch_gemm(3, x, 0, Wx + 0,     bx + 0,     4 * H,
                   h, 0, Wh + 0,     bh + 0,     3 * H,
                   g, 0, Wgh + 0,    bgh + 0,    3 * H, 0, 0, 8192);
    // r
    launch_gemm(3, x, 0, Wx + H,     bx + H,     4 * H,
                   h, 0, Wh + H,     bh + H,     3 * H,
                   g, 0, Wgh + H,    bgh + H,    3 * H, 0, 2048, 8192);
    // u: x_u is 4th block of Wx, h_u/g_u are 3rd blocks
    launch_gemm(3, x, 0, Wx + 3 * H, bx + 3 * H, 4 * H,
                   h, 0, Wh + 2 * H, bh + 2 * H, 3 * H,
                   g, 0, Wgh + 2 * H, bgh + 2 * H, 3 * H, 0, 4096, 8192);
    // cand_x: x_h (3rd block of Wx)
    launch_gemm(1, x, 0, Wx + 2 * H, bx + 2 * H, 4 * H,
                   nullptr, 0, nullptr, nullptr, 0,
                   nullptr, 0, nullptr, nullptr, 0, 0, 6144, 8192);

    int epiBlocks = (int)(((size_t)B_DIM * H_DIM / 4 + 255) / 256);
    epi1_kernel<<<epiBlocks, 256>>>(h, g, hnew);

    // Stage 2: S2 = [z2 | r2 | cand2] (ldc 6144). A0 = g_hd scratch (ahd flag).
    launch_gemm(2, nullptr, 1, Whd + 0,     bhd + 0,     3 * H,
                   g,       0, Wg + 0,      bg + 0,      2 * H,
                   nullptr, 0, nullptr,     nullptr,     0, 1, 0, 6144);
    launch_gemm(2, nullptr, 1, Whd + H,     bhd + H,     3 * H,
                   g,       0, Wg + H,      bg + H,      2 * H,
                   nullptr, 0, nullptr,     nullptr,     0, 1, 2048, 6144);
    launch_gemm(1, nullptr, 1, Whd + 2 * H, bhd + 2 * H, 3 * H,
                   nullptr, 0, nullptr,     nullptr,     0,
                   nullptr, 0, nullptr,     nullptr,     0, 1, 4096, 6144);

    epi2_kernel<<<epiBlocks, 256>>>(g, gnew);
}

// round 3
// speedup vs baseline: 2.1264x; 2.1264x over previous
#include <cuda_runtime.h>
#include <stdint.h>
#include <math.h>

#define HD   2048
#define BDIM 8192
#define BM   128
#define BN   128
#define BK   32
#define NST  3
#define SA_ST 36    // floats; 144B rows (16B-aligned, conflict-free frag loads)
#define SB_ST 136   // floats; 544B rows
#define SA_FLOATS (BM * SA_ST)          // 4608
#define SB_FLOATS (BK * SB_ST)          // 4352
#define SMEM_BYTES ((NST * (SA_FLOATS + SB_FLOATS)) * 4)  // 107520

// ---------------- device scratch ----------------
__device__ float g_S1[(size_t)BDIM * 8192];   // [z | r | u | cand_x]
__device__ float g_S2[(size_t)BDIM * 6144];   // [z2 | r2 | cand2]
__device__ float g_hd[(size_t)BDIM * HD];     // h_new - h

// ---------------- PTX helpers ----------------
#define CP_ASYNC(dst, src) \
    asm volatile("cp.async.cg.shared.global [%0], [%1], 16;" :: "r"(dst), "l"(src))
#define CP_COMMIT() asm volatile("cp.async.commit_group;" ::: "memory")
#define CP_WAIT(n)  asm volatile("cp.async.wait_group %0;" :: "n"(n) : "memory")

__device__ __forceinline__ void mma8(float c[4], const uint32_t a[4], const uint32_t b[2]) {
    asm volatile(
        "mma.sync.aligned.m16n8k8.row.col.f32.tf32.tf32.f32 "
        "{%0,%1,%2,%3}, {%4,%5,%6,%7}, {%8,%9}, {%0,%1,%2,%3};\n"
        : "+f"(c[0]), "+f"(c[1]), "+f"(c[2]), "+f"(c[3])
        : "r"(a[0]), "r"(a[1]), "r"(a[2]), "r"(a[3]), "r"(b[0]), "r"(b[1]));
}

// ---------------- GEMM args: per-gate-block slice table ----------------
struct GArgs {
    float* C;
    long long ldc;
    int nA[4];
    const float* A[4][3];     // activations [8192, 2048] K-contig
    const float* W[4][3];     // weight base + gate-block column offset
    long long ldw[4][3];
    const float* bias[4][3];  // bias base + gate-block offset
};

// C[:, blk*2048 + nloc .. ] = sum_a A_a @ W_a + bias ; 16 n-tiles per gate block
__global__ __launch_bounds__(256, 2)
void gemm_tf32_kernel(const __grid_constant__ GArgs args) {
    extern __shared__ float smem[];
    float* sA = smem;                      // [NST][SA_FLOATS]
    float* sB = smem + NST * SA_FLOATS;    // [NST][SB_FLOATS]

    const int tid  = threadIdx.x;
    const int lane = tid & 31;
    const int warp = tid >> 5;
    const int wm = warp & 1;    // 2 warps along M (64 rows each)
    const int wn = warp >> 1;   // 4 warps along N (32 cols each)

    const int blk  = blockIdx.x >> 4;
    const int nloc = (blockIdx.x & 15) << 7;    // col within gate block
    const int m0   = blockIdx.y << 7;
    const int nA   = args.nA[blk];
    const int iters = nA << 6;                  // nA * (2048/32)

    const float* Ap[3];
    const float* Wp[3];
    long long ldw[3];
#pragma unroll
    for (int a = 0; a < 3; a++) {
        Ap[a] = args.A[blk][a];
        Wp[a] = args.W[blk][a];
        ldw[a] = args.ldw[blk][a];
    }

    float acc[4][4][4];
#pragma unroll
    for (int i = 0; i < 4; i++)
#pragma unroll
        for (int j = 0; j < 4; j++)
#pragma unroll
            for (int k = 0; k < 4; k++) acc[i][j][k] = 0.f;

    // ---- async load of one BK=32 stage ----
    const int arow = tid >> 3;            // base pattern rows: 4 granule sets
    const int acol = (tid & 7) << 2;      // float col within 32
    const int brow = tid >> 5;
    const int bcol = (tid & 31) << 2;

    auto load_stage = [&](int it) {
        const int s = it % NST;
        const int a = it >> 6;
        const int k0 = (it & 63) << 5;
        const float* Abase = Ap[a] + (size_t)m0 * HD + k0;
        const float* Wbase = Wp[a] + (size_t)k0 * ldw[a] + nloc;
        float* dA = sA + s * SA_FLOATS;
        float* dB = sB + s * SB_FLOATS;
#pragma unroll
        for (int i = 0; i < 4; i++) {
            const int r = arow + i * 32;   // 0..127
            uint32_t dst = (uint32_t)__cvta_generic_to_shared(dA + r * SA_ST + acol);
            CP_ASYNC(dst, Abase + (size_t)r * HD + acol);
        }
#pragma unroll
        for (int i = 0; i < 4; i++) {
            const int r = brow + i * 8;    // 0..31
            const int c = bcol;            // covers 0..124 per 32 lanes? (tid&31)*4
            uint32_t dst = (uint32_t)__cvta_generic_to_shared(dB + r * SB_ST + c);
            CP_ASYNC(dst, Wbase + (size_t)r * ldw[a] + c);
        }
        CP_COMMIT();
    };

    auto compute = [&](int s) {
        const float* cA = sA + s * SA_FLOATS;
        const float* cB = sB + s * SB_FLOATS;
#pragma unroll
        for (int ks = 0; ks < 4; ks++) {
            uint32_t af[4][4], bf[4][2];
            const int kc = ks * 8 + (lane & 3);
#pragma unroll
            for (int mt = 0; mt < 4; mt++) {
                const int r = wm * 64 + mt * 16 + (lane >> 2);
                af[mt][0] = __float_as_uint(cA[r * SA_ST + kc]);
                af[mt][1] = __float_as_uint(cA[(r + 8) * SA_ST + kc]);
                af[mt][2] = __float_as_uint(cA[r * SA_ST + kc + 4]);
                af[mt][3] = __float_as_uint(cA[(r + 8) * SA_ST + kc + 4]);
            }
#pragma unroll
            for (int nt = 0; nt < 4; nt++) {
                const int c = wn * 32 + nt * 8 + (lane >> 2);
                bf[nt][0] = __float_as_uint(cB[kc * SB_ST + c]);
                bf[nt][1] = __float_as_uint(cB[(kc + 4) * SB_ST + c]);
            }
#pragma unroll
            for (int mt = 0; mt < 4; mt++)
#pragma unroll
                for (int nt = 0; nt < 4; nt++)
                    mma8(acc[mt][nt], af[mt], bf[nt]);
        }
    };

    // prologue: stages 0, 1
    load_stage(0);
    load_stage(1);

    for (int it = 0; it < iters; it++) {
        CP_WAIT(1);
        __syncthreads();
        if (it + 2 < iters) load_stage(it + 2);
        compute(it % NST);
    }

    // epilogue: bias + store
    const int cbase = (blockIdx.x << 7);  // global C col of this tile
#pragma unroll
    for (int nt = 0; nt < 4; nt++) {
        const int cl = wn * 32 + nt * 8 + 2 * (lane & 3);
        float bs0 = 0.f, bs1 = 0.f;
        for (int a = 0; a < nA; a++) {
            bs0 += args.bias[blk][a][nloc + cl];
            bs1 += args.bias[blk][a][nloc + cl + 1];
        }
#pragma unroll
        for (int mt = 0; mt < 4; mt++) {
            const int r = m0 + wm * 64 + mt * 16 + (lane >> 2);
            float2 v0 = make_float2(acc[mt][nt][0] + bs0, acc[mt][nt][1] + bs1);
            float2 v1 = make_float2(acc[mt][nt][2] + bs0, acc[mt][nt][3] + bs1);
            *(float2*)(args.C + (size_t)r * args.ldc + cbase + cl) = v0;
            *(float2*)(args.C + (size_t)(r + 8) * args.ldc + cbase + cl) = v1;
        }
    }
}

// ---------------- elementwise epilogues ----------------
__device__ __forceinline__ float sigm(float x) { return 1.f / (1.f + expf(-x)); }

__global__ void epi1_kernel(const float* __restrict__ h, const float* __restrict__ g,
                            float* __restrict__ hnew) {
    size_t e0 = ((size_t)blockIdx.x * blockDim.x + threadIdx.x) * 4;
    size_t b = e0 >> 11, j = e0 & 2047;
    const float* row = g_S1 + b * 8192 + j;
    float4 zp = *(const float4*)(row);
    float4 rp = *(const float4*)(row + 2048);
    float4 up = *(const float4*)(row + 4096);
    float4 cp = *(const float4*)(row + 6144);
    float4 hv = *(const float4*)(h + e0);
    float4 gv = *(const float4*)(g + e0);
    float4 hn, hd;
#define DO1(f)                                                     \
    {                                                              \
        float z = sigm(zp.f), r = sigm(rp.f), uu = sigm(up.f);     \
        float cand = tanhf(cp.f + r * hv.f + uu * gv.f);           \
        hn.f = (1.f - z) * hv.f + z * cand;                        \
        hd.f = hn.f - hv.f;                                        \
    }
    DO1(x) DO1(y) DO1(z) DO1(w)
#undef DO1
    *(float4*)(hnew + e0) = hn;
    *(float4*)(g_hd + e0) = hd;
}

__global__ void epi2_kernel(const float* __restrict__ g, float* __restrict__ gnew) {
    size_t e0 = ((size_t)blockIdx.x * blockDim.x + threadIdx.x) * 4;
    size_t b = e0 >> 11, j = e0 & 2047;
    const float* row = g_S2 + b * 6144 + j;
    float4 zp = *(const float4*)(row);
    float4 rp = *(const float4*)(row + 2048);
    float4 cp = *(const float4*)(row + 4096);
    float4 gv = *(const float4*)(g + e0);
    float4 gn;
#define DO2(f)                                       \
    {                                                \
        float z = sigm(zp.f), r = sigm(rp.f);        \
        float cand = tanhf(cp.f + r * gv.f);         \
        gn.f = (1.f - z) * gv.f + z * cand;          \
    }
    DO2(x) DO2(y) DO2(z) DO2(w)
#undef DO2
    *(float4*)(gnew + e0) = gn;
}

// ---------------- host ----------------
extern "C" void kernel_launch(void* const* d_in, const int* in_sizes, int n_in,
                              void* d_out, int out_size) {
    (void)in_sizes; (void)n_in; (void)out_size;
    const float* x   = (const float*)d_in[0];
    const float* h   = (const float*)d_in[1];
    const float* g   = (const float*)d_in[2];
    const float* Wx  = (const float*)d_in[3];
    const float* bx  = (const float*)d_in[4];
    const float* Wh  = (const float*)d_in[5];
    const float* bh  = (const float*)d_in[6];
    const float* Wgh = (const float*)d_in[7];
    const float* bgh = (const float*)d_in[8];
    const float* Whd = (const float*)d_in[9];
    const float* bhd = (const float*)d_in[10];
    const float* Wg  = (const float*)d_in[11];
    const float* bg  = (const float*)d_in[12];

    float* out  = (float*)d_out;
    float* hnew = out;
    float* gnew = out + (size_t)BDIM * HD;

    void *pS1, *pS2, *pHd;
    cudaGetSymbolAddress(&pS1, g_S1);
    cudaGetSymbolAddress(&pS2, g_S2);
    cudaGetSymbolAddress(&pHd, g_hd);

    cudaFuncSetAttribute(gemm_tf32_kernel, cudaFuncAttributeMaxDynamicSharedMemorySize,
                         SMEM_BYTES);

    const int H = HD;

    // Stage 1: S1 = [z | r | u | cand_x], ldc 8192
    {
        GArgs a;
        a.C = (float*)pS1; a.ldc = 8192;
        int nA[4] = {3, 3, 3, 1};
        const float* A[4][3] = {{x, h, g}, {x, h, g}, {x, h, g}, {x, x, x}};
        const float* W[4][3] = {{Wx, Wh, Wgh},
                                {Wx + H, Wh + H, Wgh + H},
                                {Wx + 3 * H, Wh + 2 * H, Wgh + 2 * H},
                                {Wx + 2 * H, Wx, Wx}};
        long long L[4][3] = {{4 * H, 3 * H, 3 * H},
                             {4 * H, 3 * H, 3 * H},
                             {4 * H, 3 * H, 3 * H},
                             {4 * H, 4 * H, 4 * H}};
        const float* Bp[4][3] = {{bx, bh, bgh},
                                 {bx + H, bh + H, bgh + H},
                                 {bx + 3 * H, bh + 2 * H, bgh + 2 * H},
                                 {bx + 2 * H, bx, bx}};
        for (int i = 0; i < 4; i++) {
            a.nA[i] = nA[i];
            for (int j = 0; j < 3; j++) {
                a.A[i][j] = A[i][j]; a.W[i][j] = W[i][j];
                a.ldw[i][j] = L[i][j]; a.bias[i][j] = Bp[i][j];
            }
        }
        gemm_tf32_kernel<<<dim3(64, 64), 256, SMEM_BYTES>>>(a);
    }

    unsigned epiBlocks = (unsigned)(((size_t)BDIM * HD / 4) / 256);
    epi1_kernel<<<epiBlocks, 256>>>(h, g, hnew);

    // Stage 2: S2 = [z2 | r2 | cand2], ldc 6144. A0 = g_hd
    {
        GArgs a;
        a.C = (float*)pS2; a.ldc = 6144;
        const float* hd = (const float*)pHd;
        int nA[4] = {2, 2, 1, 1};
        const float* A[4][3] = {{hd, g, hd}, {hd, g, hd}, {hd, hd, hd}, {hd, hd, hd}};
        const float* W[4][3] = {{Whd, Wg, Whd},
                                {Whd + H, Wg + H, Whd},
                                {Whd + 2 * H, Whd, Whd},
                                {Whd, Whd, Whd}};
        long long L[4][3] = {{3 * H, 2 * H, 3 * H},
                             {3 * H, 2 * H, 3 * H},
                             {3 * H, 3 * H, 3 * H},
                             {3 * H, 3 * H, 3 * H}};
        const float* Bp[4][3] = {{bhd, bg, bhd},
                                 {bhd + H, bg + H, bhd},
                                 {bhd + 2 * H, bhd, bhd},
                                 {bhd, bhd, bhd}};
        for (int i = 0; i < 4; i++) {
            a.nA[i] = nA[i];
            for (int j = 0; j < 3; j++) {
                a.A[i][j] = A[i][j]; a.W[i][j] = W[i][j];
                a.ldw[i][j] = L[i][j]; a.bias[i][j] = Bp[i][j];
            }
        }
        gemm_tf32_kernel<<<dim3(48, 64), 256, SMEM_BYTES>>>(a);
    }

    epi2_kernel<<<epiBlocks, 256>>>(g, gnew);
}

// round 4
// speedup vs baseline: 2.3370x; 1.0990x over previous
#include <cuda_runtime.h>
#include <stdint.h>
#include <math.h>

#define HD   2048
#define BDIM 8192
#define BM   128
#define BN   256
#define BK   32
#define NST  3
#define SA_ST 36    // floats; conflict-free A frag loads (4r+kc mod 32)
#define SB_ST 264   // floats; conflict-free B frag loads (8kc+c mod 32)
#define SA_FLOATS (BM * SA_ST)               // 4608
#define SB_FLOATS (BK * SB_ST)               // 8448
#define SMEM_BYTES ((NST * (SA_FLOATS + SB_FLOATS)) * 4)  // 156672

// ---------------- device scratch ----------------
__device__ float g_S1[(size_t)BDIM * 8192];   // [z | r | u | cand_x]
__device__ float g_S2[(size_t)BDIM * 6144];   // [z2 | r2 | cand2]
__device__ float g_hd[(size_t)BDIM * HD];     // h_new - h

// ---------------- PTX helpers ----------------
#define CP_ASYNC(dst, src) \
    asm volatile("cp.async.cg.shared.global [%0], [%1], 16;" :: "r"(dst), "l"(src))
#define CP_COMMIT() asm volatile("cp.async.commit_group;" ::: "memory")
#define CP_WAIT(n)  asm volatile("cp.async.wait_group %0;" :: "n"(n) : "memory")

__device__ __forceinline__ void mma8(float c[4], const uint32_t a[4], const uint32_t b[2]) {
    asm volatile(
        "mma.sync.aligned.m16n8k8.row.col.f32.tf32.tf32.f32 "
        "{%0,%1,%2,%3}, {%4,%5,%6,%7}, {%8,%9}, {%0,%1,%2,%3};\n"
        : "+f"(c[0]), "+f"(c[1]), "+f"(c[2]), "+f"(c[3])
        : "r"(a[0]), "r"(a[1]), "r"(a[2]), "r"(a[3]), "r"(b[0]), "r"(b[1]));
}

// ---------------- GEMM args ----------------
struct GArgs {
    float* C;
    long long ldc;
    int nA[4];
    const float* A[4][3];
    const float* W[4][3];
    long long ldw[4][3];
    const float* bias[4][3];
};

// grid: x = M tiles (64), y = N tiles. blk = y>>3 (gate block), nloc = (y&7)*256
__global__ __launch_bounds__(256, 1)
void gemm_tf32_kernel(const __grid_constant__ GArgs args) {
    extern __shared__ float smem[];
    float* sA = smem;                      // [NST][SA_FLOATS]
    float* sB = smem + NST * SA_FLOATS;    // [NST][SB_FLOATS]

    const int tid  = threadIdx.x;
    const int lane = tid & 31;
    const int warp = tid >> 5;
    const int wm = warp & 1;    // 2 warps along M (64 rows)
    const int wn = warp >> 1;   // 4 warps along N (64 cols)

    const int m0   = blockIdx.x << 7;
    const int blk  = blockIdx.y >> 3;
    const int nloc = (blockIdx.y & 7) << 8;
    const int nA   = args.nA[blk];
    const int iters = nA << 6;              // nA * (2048/32)

    const float* Ap[3];
    const float* Wp[3];
    long long ldw[3];
#pragma unroll
    for (int a = 0; a < 3; a++) {
        Ap[a] = args.A[blk][a];
        Wp[a] = args.W[blk][a];
        ldw[a] = args.ldw[blk][a];
    }

    float acc[4][8][4];
#pragma unroll
    for (int i = 0; i < 4; i++)
#pragma unroll
        for (int j = 0; j < 8; j++)
#pragma unroll
            for (int k = 0; k < 4; k++) acc[i][j][k] = 0.f;

    // ---- async load mapping ----
    const int arow = tid >> 3;            // 0..31 (A rows, +32*i)
    const int acol = (tid & 7) << 2;      // 0..28
    const int brow = tid >> 6;            // 0..3  (B rows, +4*i)
    const int bcol = (tid & 63) << 2;     // 0..252

    auto load_stage = [&](int it) {
        const int s = it % NST;
        const int a = it >> 6;
        const int k0 = (it & 63) << 5;
        const float* Abase = Ap[a] + (size_t)m0 * HD + k0;
        const float* Wbase = Wp[a] + (size_t)k0 * ldw[a] + nloc;
        float* dA = sA + s * SA_FLOATS;
        float* dB = sB + s * SB_FLOATS;
#pragma unroll
        for (int i = 0; i < 4; i++) {
            const int r = arow + i * 32;
            uint32_t dst = (uint32_t)__cvta_generic_to_shared(dA + r * SA_ST + acol);
            CP_ASYNC(dst, Abase + (size_t)r * HD + acol);
        }
#pragma unroll
        for (int i = 0; i < 8; i++) {
            const int r = brow + i * 4;
            uint32_t dst = (uint32_t)__cvta_generic_to_shared(dB + r * SB_ST + bcol);
            CP_ASYNC(dst, Wbase + (size_t)r * ldw[a] + bcol);
        }
        CP_COMMIT();
    };

    auto compute = [&](int s) {
        const float* cA = sA + s * SA_FLOATS;
        const float* cB = sB + s * SB_FLOATS;
#pragma unroll
        for (int ks = 0; ks < 4; ks++) {
            uint32_t af[4][4], bf[8][2];
            const int kc = ks * 8 + (lane & 3);
#pragma unroll
            for (int mt = 0; mt < 4; mt++) {
                const int r = wm * 64 + mt * 16 + (lane >> 2);
                af[mt][0] = __float_as_uint(cA[r * SA_ST + kc]);
                af[mt][1] = __float_as_uint(cA[(r + 8) * SA_ST + kc]);
                af[mt][2] = __float_as_uint(cA[r * SA_ST + kc + 4]);
                af[mt][3] = __float_as_uint(cA[(r + 8) * SA_ST + kc + 4]);
            }
#pragma unroll
            for (int nt = 0; nt < 8; nt++) {
                const int c = wn * 64 + nt * 8 + (lane >> 2);
                bf[nt][0] = __float_as_uint(cB[kc * SB_ST + c]);
                bf[nt][1] = __float_as_uint(cB[(kc + 4) * SB_ST + c]);
            }
#pragma unroll
            for (int mt = 0; mt < 4; mt++)
#pragma unroll
                for (int nt = 0; nt < 8; nt++)
                    mma8(acc[mt][nt], af[mt], bf[nt]);
        }
    };

    load_stage(0);
    load_stage(1);

#pragma unroll 1
    for (int it = 0; it < iters; it++) {
        CP_WAIT(1);
        __syncthreads();
        if (it + 2 < iters) load_stage(it + 2);
        compute(it % NST);
    }

    // epilogue: bias + store
    const int cbase = blockIdx.y << 8;
#pragma unroll
    for (int nt = 0; nt < 8; nt++) {
        const int cl = wn * 64 + nt * 8 + 2 * (lane & 3);
        float bs0 = 0.f, bs1 = 0.f;
        for (int a = 0; a < nA; a++) {
            bs0 += args.bias[blk][a][nloc + cl];
            bs1 += args.bias[blk][a][nloc + cl + 1];
        }
#pragma unroll
        for (int mt = 0; mt < 4; mt++) {
            const int r = m0 + wm * 64 + mt * 16 + (lane >> 2);
            float2 v0 = make_float2(acc[mt][nt][0] + bs0, acc[mt][nt][1] + bs1);
            float2 v1 = make_float2(acc[mt][nt][2] + bs0, acc[mt][nt][3] + bs1);
            *(float2*)(args.C + (size_t)r * args.ldc + cbase + cl) = v0;
            *(float2*)(args.C + (size_t)(r + 8) * args.ldc + cbase + cl) = v1;
        }
    }
}

// ---------------- elementwise epilogues ----------------
__device__ __forceinline__ float sigm(float x) { return 1.f / (1.f + expf(-x)); }

__global__ void epi1_kernel(const float* __restrict__ h, const float* __restrict__ g,
                            float* __restrict__ hnew) {
    size_t e0 = ((size_t)blockIdx.x * blockDim.x + threadIdx.x) * 4;
    size_t b = e0 >> 11, j = e0 & 2047;
    const float* row = g_S1 + b * 8192 + j;
    float4 zp = *(const float4*)(row);
    float4 rp = *(const float4*)(row + 2048);
    float4 up = *(const float4*)(row + 4096);
    float4 cp = *(const float4*)(row + 6144);
    float4 hv = *(const float4*)(h + e0);
    float4 gv = *(const float4*)(g + e0);
    float4 hn, hd;
#define DO1(f)                                                     \
    {                                                              \
        float z = sigm(zp.f), r = sigm(rp.f), uu = sigm(up.f);     \
        float cand = tanhf(cp.f + r * hv.f + uu * gv.f);           \
        hn.f = (1.f - z) * hv.f + z * cand;                        \
        hd.f = hn.f - hv.f;                                        \
    }
    DO1(x) DO1(y) DO1(z) DO1(w)
#undef DO1
    *(float4*)(hnew + e0) = hn;
    *(float4*)(g_hd + e0) = hd;
}

__global__ void epi2_kernel(const float* __restrict__ g, float* __restrict__ gnew) {
    size_t e0 = ((size_t)blockIdx.x * blockDim.x + threadIdx.x) * 4;
    size_t b = e0 >> 11, j = e0 & 2047;
    const float* row = g_S2 + b * 6144 + j;
    float4 zp = *(const float4*)(row);
    float4 rp = *(const float4*)(row + 2048);
    float4 cp = *(const float4*)(row + 4096);
    float4 gv = *(const float4*)(g + e0);
    float4 gn;
#define DO2(f)                                       \
    {                                                \
        float z = sigm(zp.f), r = sigm(rp.f);        \
        float cand = tanhf(cp.f + r * gv.f);         \
        gn.f = (1.f - z) * gv.f + z * cand;          \
    }
    DO2(x) DO2(y) DO2(z) DO2(w)
#undef DO2
    *(float4*)(gnew + e0) = gn;
}

// ---------------- host ----------------
extern "C" void kernel_launch(void* const* d_in, const int* in_sizes, int n_in,
                              void* d_out, int out_size) {
    (void)in_sizes; (void)n_in; (void)out_size;
    const float* x   = (const float*)d_in[0];
    const float* h   = (const float*)d_in[1];
    const float* g   = (const float*)d_in[2];
    const float* Wx  = (const float*)d_in[3];
    const float* bx  = (const float*)d_in[4];
    const float* Wh  = (const float*)d_in[5];
    const float* bh  = (const float*)d_in[6];
    const float* Wgh = (const float*)d_in[7];
    const float* bgh = (const float*)d_in[8];
    const float* Whd = (const float*)d_in[9];
    const float* bhd = (const float*)d_in[10];
    const float* Wg  = (const float*)d_in[11];
    const float* bg  = (const float*)d_in[12];

    float* out  = (float*)d_out;
    float* hnew = out;
    float* gnew = out + (size_t)BDIM * HD;

    void *pS1, *pS2, *pHd;
    cudaGetSymbolAddress(&pS1, g_S1);
    cudaGetSymbolAddress(&pS2, g_S2);
    cudaGetSymbolAddress(&pHd, g_hd);

    cudaFuncSetAttribute(gemm_tf32_kernel, cudaFuncAttributeMaxDynamicSharedMemorySize,
                         SMEM_BYTES);

    const int H = HD;

    // Stage 1: S1 = [z | r | u | cand_x], ldc 8192
    {
        GArgs a;
        a.C = (float*)pS1; a.ldc = 8192;
        int nA[4] = {3, 3, 3, 1};
        const float* A[4][3] = {{x, h, g}, {x, h, g}, {x, h, g}, {x, x, x}};
        const float* W[4][3] = {{Wx, Wh, Wgh},
                                {Wx + H, Wh + H, Wgh + H},
                                {Wx + 3 * H, Wh + 2 * H, Wgh + 2 * H},
                                {Wx + 2 * H, Wx, Wx}};
        long long L[4][3] = {{4 * H, 3 * H, 3 * H},
                             {4 * H, 3 * H, 3 * H},
                             {4 * H, 3 * H, 3 * H},
                             {4 * H, 4 * H, 4 * H}};
        const float* Bp[4][3] = {{bx, bh, bgh},
                                 {bx + H, bh + H, bgh + H},
                                 {bx + 3 * H, bh + 2 * H, bgh + 2 * H},
                                 {bx + 2 * H, bx, bx}};
        for (int i = 0; i < 4; i++) {
            a.nA[i] = nA[i];
            for (int j = 0; j < 3; j++) {
                a.A[i][j] = A[i][j]; a.W[i][j] = W[i][j];
                a.ldw[i][j] = L[i][j]; a.bias[i][j] = Bp[i][j];
            }
        }
        gemm_tf32_kernel<<<dim3(64, 32), 256, SMEM_BYTES>>>(a);
    }

    unsigned epiBlocks = (unsigned)(((size_t)BDIM * HD / 4) / 256);
    epi1_kernel<<<epiBlocks, 256>>>(h, g, hnew);

    // Stage 2: S2 = [z2 | r2 | cand2], ldc 6144
    {
        GArgs a;
        a.C = (float*)pS2; a.ldc = 6144;
        const float* hd = (const float*)pHd;
        int nA[4] = {2, 2, 1, 1};
        const float* A[4][3] = {{hd, g, hd}, {hd, g, hd}, {hd, hd, hd}, {hd, hd, hd}};
        const float* W[4][3] = {{Whd, Wg, Whd},
                                {Whd + H, Wg + H, Whd},
                                {Whd + 2 * H, Whd, Whd},
                                {Whd, Whd, Whd}};
        long long L[4][3] = {{3 * H, 2 * H, 3 * H},
                             {3 * H, 2 * H, 3 * H},
                             {3 * H, 3 * H, 3 * H},
                             {3 * H, 3 * H, 3 * H}};
        const float* Bp[4][3] = {{bhd, bg, bhd},
                                 {bhd + H, bg + H, bhd},
                                 {bhd + 2 * H, bhd, bhd},
                                 {bhd, bhd, bhd}};
        for (int i = 0; i < 4; i++) {
            a.nA[i] = nA[i];
            for (int j = 0; j < 3; j++) {
                a.A[i][j] = A[i][j]; a.W[i][j] = W[i][j];
                a.ldw[i][j] = L[i][j]; a.bias[i][j] = Bp[i][j];
            }
        }
        gemm_tf32_kernel<<<dim3(64, 24), 256, SMEM_BYTES>>>(a);
    }

    epi2_kernel<<<epiBlocks, 256>>>(g, gnew);
}